// round 4
// baseline (speedup 1.0000x reference)
#include <cuda_runtime.h>

#define DIM  768
#define DIM3 2304
#define MAX_S 2048
#define MAX_E 32768
#define MAX_N 100000
#define MAX_R 1000

// ---------------- device scratch (no allocs allowed) ----------------
__device__ float g_sub [MAX_S * DIM];        // tanh(mask@W_sub^T+b)          6.3 MB
__device__ float g_r0  [MAX_S * DIM];        // GRU(enc, sub)                 6.3 MB
__device__ float g_gh  [MAX_S * DIM3];       // sub@W_hh^T+b_hh              18.9 MB
__device__ float g_gi0 [MAX_S * DIM3];       // r0@W_ih^T+b_ih               18.9 MB
__device__ float g_ghR [MAX_R * DIM3];       // rel_emb@W_hh^T+b_hh           9.2 MB
__device__ float g_rj  [MAX_E * DIM];        // per-edge GRU out            100.7 MB
__device__ float g_obj [MAX_E * DIM];        // tanh(rj@W_obj^T+b)          100.7 MB
__device__ float g_gi_enc[DIM3];             // enc@W_ih^T+b_ih (one row)
__device__ int   g_best[MAX_N];              // winning timestamp per node
__device__ int   g_seedpos[MAX_N];           // node -> seed position

// ---------------- packed f32x2 helpers ----------------
__device__ __forceinline__ unsigned long long rep2(float a) {
    unsigned long long r;
    asm("mov.b64 %0, {%1, %1};" : "=l"(r) : "f"(a));
    return r;
}
__device__ __forceinline__ void fma2(unsigned long long &d,
                                     unsigned long long a, unsigned long long b) {
    asm("fma.rn.f32x2 %0, %1, %2, %0;" : "+l"(d) : "l"(a), "l"(b));
}
__device__ __forceinline__ float2 unp2(unsigned long long v) {
    float x, y;
    asm("mov.b64 {%0, %1}, %2;" : "=f"(x), "=f"(y) : "l"(v));
    return make_float2(x, y);
}

// ---------------- C[M,N] = act(A[M,K] @ W[N,K]^T + bias) ----------------
// A row-major [M,K], W row-major [N,K] (both K contiguous). N % 128 == 0,
// K % 8 == 0. M arbitrary (guarded). BM=BN=128, BK=8, 256 threads, 8x8/thread.
template<int ACT>
__global__ __launch_bounds__(256, 2)
void gemm_nt(const float* __restrict__ A, const float* __restrict__ W,
             const float* __restrict__ bias, float* __restrict__ C,
             int M, int N, int K)
{
    __shared__ float As[8][128];
    __shared__ float Bs[8][128];

    const int tid = threadIdx.x;
    const int tx = tid & 15;        // 0..15 -> col group
    const int ty = tid >> 4;        // 0..15 -> row group
    const int row0 = blockIdx.y * 128;
    const int col0 = blockIdx.x * 128;

    const int lr = tid >> 1;        // loader row 0..127
    const int lc = (tid & 1) << 2;  // loader col 0 or 4

    unsigned long long acc[8][4];
#pragma unroll
    for (int i = 0; i < 8; i++)
#pragma unroll
        for (int p = 0; p < 4; p++) acc[i][p] = 0ULL;

    const bool aok = (row0 + lr) < M;
    const float* aptr = A + (size_t)(row0 + lr) * K + lc;
    const float* bptr = W + (size_t)(col0 + lr) * K + lc;

    float4 av = aok ? *(const float4*)aptr : make_float4(0.f, 0.f, 0.f, 0.f);
    float4 bv = *(const float4*)bptr;

    for (int k0 = 0; k0 < K; k0 += 8) {
        As[lc + 0][lr] = av.x; As[lc + 1][lr] = av.y;
        As[lc + 2][lr] = av.z; As[lc + 3][lr] = av.w;
        Bs[lc + 0][lr] = bv.x; Bs[lc + 1][lr] = bv.y;
        Bs[lc + 2][lr] = bv.z; Bs[lc + 3][lr] = bv.w;
        __syncthreads();

        if (k0 + 8 < K) {  // prefetch next tile while computing
            av = aok ? *(const float4*)(aptr + k0 + 8) : make_float4(0.f, 0.f, 0.f, 0.f);
            bv = *(const float4*)(bptr + k0 + 8);
        }

#pragma unroll
        for (int k = 0; k < 8; k++) {
            const float4 a0 = *(const float4*)&As[k][ty * 8];
            const float4 a1 = *(const float4*)&As[k][ty * 8 + 4];
            const ulonglong2 b01 = *(const ulonglong2*)&Bs[k][tx * 8];
            const ulonglong2 b23 = *(const ulonglong2*)&Bs[k][tx * 8 + 4];
            unsigned long long ap[8];
            ap[0] = rep2(a0.x); ap[1] = rep2(a0.y); ap[2] = rep2(a0.z); ap[3] = rep2(a0.w);
            ap[4] = rep2(a1.x); ap[5] = rep2(a1.y); ap[6] = rep2(a1.z); ap[7] = rep2(a1.w);
            unsigned long long bp[4];
            bp[0] = b01.x; bp[1] = b01.y; bp[2] = b23.x; bp[3] = b23.y;
#pragma unroll
            for (int i = 0; i < 8; i++) {
#pragma unroll
                for (int p = 0; p < 4; p++) fma2(acc[i][p], ap[i], bp[p]);
            }
        }
        __syncthreads();
    }

    // epilogue
    const float* brow = bias + col0 + tx * 8;
    float bb[8];
#pragma unroll
    for (int j = 0; j < 8; j++) bb[j] = brow[j];

#pragma unroll
    for (int i = 0; i < 8; i++) {
        int r = row0 + ty * 8 + i;
        if (r >= M) continue;
        float4 o0, o1;
        float2 u;
        u = unp2(acc[i][0]); o0.x = u.x + bb[0]; o0.y = u.y + bb[1];
        u = unp2(acc[i][1]); o0.z = u.x + bb[2]; o0.w = u.y + bb[3];
        u = unp2(acc[i][2]); o1.x = u.x + bb[4]; o1.y = u.y + bb[5];
        u = unp2(acc[i][3]); o1.z = u.x + bb[6]; o1.w = u.y + bb[7];
        if (ACT) {
            o0.x = tanhf(o0.x); o0.y = tanhf(o0.y); o0.z = tanhf(o0.z); o0.w = tanhf(o0.w);
            o1.x = tanhf(o1.x); o1.y = tanhf(o1.y); o1.z = tanhf(o1.z); o1.w = tanhf(o1.w);
        }
        float* crow = C + (size_t)r * N + col0 + tx * 8;
        *(float4*)crow       = o0;
        *(float4*)(crow + 4) = o1;
    }
}

// ---------------- gi_enc = enc @ W_ih^T + b_ih (one row, 2304 outputs) ----------------
__global__ void k_gi_enc(const float* __restrict__ enc,
                         const float* __restrict__ W_ih,
                         const float* __restrict__ b_ih)
{
    int j = blockIdx.x * 8 + (threadIdx.x >> 5);
    int lane = threadIdx.x & 31;
    if (j >= DIM3) return;
    const float* w = W_ih + (size_t)j * DIM;
    float s = 0.f;
#pragma unroll
    for (int k = lane * 4; k < DIM; k += 128) {
        float4 wv = *(const float4*)(w + k);
        float4 ev = *(const float4*)(enc + k);
        s += wv.x * ev.x + wv.y * ev.y + wv.z * ev.z + wv.w * ev.w;
    }
#pragma unroll
    for (int o = 16; o; o >>= 1) s += __shfl_xor_sync(0xffffffffu, s, o);
    if (lane == 0) g_gi_enc[j] = s + b_ih[j];
}

__device__ __forceinline__ float sigm(float x) {
    return 1.f / (1.f + __expf(-x));
}
__device__ __forceinline__ float gru1(float ir, float iz, float in_,
                                      float hr, float hz, float hn, float h) {
    float r = sigm(ir + hr);
    float z = sigm(iz + hz);
    float n = tanhf(in_ + r * hn);
    return (1.f - z) * n + z * h;
}

// ---------------- r0 = GRU combine (gi_enc broadcast, gh = g_gh, h = g_sub) ----------------
__global__ void k_gru_r0(int S)
{
    int idx = blockIdx.x * blockDim.x + threadIdx.x;
    if (idx >= S * DIM) return;
    int s = idx / DIM;
    int d = idx - s * DIM;
    const float* gh = g_gh + (size_t)s * DIM3;
    float v = gru1(g_gi_enc[d], g_gi_enc[DIM + d], g_gi_enc[2 * DIM + d],
                   gh[d], gh[DIM + d], gh[2 * DIM + d], g_sub[idx]);
    g_r0[idx] = v;
}

// ---------------- timestamp machinery ----------------
__global__ void k_init(int N)
{
    int i = blockIdx.x * blockDim.x + threadIdx.x;
    if (i < N) { g_best[i] = -1; g_seedpos[i] = -1; }
}
__global__ void k_seed(const int* __restrict__ seeds, int S, int stride)
{
    int s = blockIdx.x * blockDim.x + threadIdx.x;
    if (s >= S) return;
    int node = seeds[s];
    g_seedpos[node] = s;
    atomicMax(&g_best[node], s * stride);
}
__global__ void k_edge(const int* __restrict__ heads, const int* __restrict__ tails,
                       int E, int stride)
{
    int e = blockIdx.x * blockDim.x + threadIdx.x;
    if (e >= E) return;
    int pos = g_seedpos[heads[e]];
    int t = pos * stride + 1 + e;       // pos==-1 -> negative, never beats -1 init
    atomicMax(&g_best[tails[e]], t);
}

// ---------------- per-edge GRU: rj[e] = GRU(gi0[head], ghR[type], h=rel[type]) ------------
__global__ void k_rj(const int* __restrict__ heads, const int* __restrict__ types,
                     const float* __restrict__ rel)
{
    int e = blockIdx.x;
    int h = heads[e];
    int t = types[e];
    const float* gi = g_gi0 + (size_t)h * DIM3;
    const float* gh = g_ghR + (size_t)t * DIM3;
    const float* rl = rel + (size_t)t * DIM;
    int d = threadIdx.x * 4;            // 192 threads * 4 = 768
    float4 ir  = *(const float4*)(gi + d);
    float4 iz  = *(const float4*)(gi + DIM + d);
    float4 in_ = *(const float4*)(gi + 2 * DIM + d);
    float4 hr  = *(const float4*)(gh + d);
    float4 hz  = *(const float4*)(gh + DIM + d);
    float4 hn  = *(const float4*)(gh + 2 * DIM + d);
    float4 hh  = *(const float4*)(rl + d);
    float4 o;
    o.x = gru1(ir.x, iz.x, in_.x, hr.x, hz.x, hn.x, hh.x);
    o.y = gru1(ir.y, iz.y, in_.y, hr.y, hz.y, hn.y, hh.y);
    o.z = gru1(ir.z, iz.z, in_.z, hr.z, hz.z, hn.z, hh.z);
    o.w = gru1(ir.w, iz.w, in_.w, hr.w, hz.w, hn.w, hh.w);
    *(float4*)(g_rj + (size_t)e * DIM + d) = o;
}

// ---------------- output: decode winner timestamp, gather ----------------
__global__ void k_out(const int* __restrict__ node2node, const int* __restrict__ old_nd,
                      const float* __restrict__ defa, float* __restrict__ out, int stride)
{
    int nrow = blockIdx.x;
    int id = node2node[old_nd[nrow]];
    int b = g_best[id];
    const float* src;
    if (b < 0) {
        src = defa + (size_t)nrow * DIM;
    } else {
        int q = b / stride;
        int rem = b - q * stride;
        src = (rem == 0) ? (g_sub + (size_t)q * DIM)
                         : (g_obj + (size_t)(rem - 1) * DIM);
    }
    int d = threadIdx.x * 4;            // 192 threads
    *(float4*)(out + (size_t)nrow * DIM + d) = *(const float4*)(src + d);
}

// ---------------- host ----------------
extern "C" void kernel_launch(void* const* d_in, const int* in_sizes, int n_in,
                              void* d_out, int out_size)
{
    const float* enc   = (const float*)d_in[0];
    const float* smask = (const float*)d_in[1];
    const int*   seeds = (const int*)  d_in[2];
    const int*   ehead = (const int*)  d_in[3];
    const int*   etail = (const int*)  d_in[4];
    const int*   etype = (const int*)  d_in[5];
    const int*   n2n   = (const int*)  d_in[6];
    const int*   oldnd = (const int*)  d_in[7];
    const float* relE  = (const float*)d_in[8];
    const float* W_sub = (const float*)d_in[9];
    const float* b_sub = (const float*)d_in[10];
    const float* W_obj = (const float*)d_in[11];
    const float* b_obj = (const float*)d_in[12];
    const float* W_ih  = (const float*)d_in[13];
    const float* W_hh  = (const float*)d_in[14];
    const float* b_ih  = (const float*)d_in[15];
    const float* b_hh  = (const float*)d_in[16];
    const float* defa  = (const float*)d_in[17];
    float* out = (float*)d_out;

    const int S = in_sizes[2];
    const int E = in_sizes[3];
    const int N = in_sizes[6];
    const int R = in_sizes[8] / DIM;
    const int stride = E + 1;

    float *p_sub, *p_r0, *p_gh, *p_gi0, *p_ghR, *p_rj, *p_obj;
    cudaGetSymbolAddress((void**)&p_sub, g_sub);
    cudaGetSymbolAddress((void**)&p_r0,  g_r0);
    cudaGetSymbolAddress((void**)&p_gh,  g_gh);
    cudaGetSymbolAddress((void**)&p_gi0, g_gi0);
    cudaGetSymbolAddress((void**)&p_ghR, g_ghR);
    cudaGetSymbolAddress((void**)&p_rj,  g_rj);
    cudaGetSymbolAddress((void**)&p_obj, g_obj);

    // timestamps init + scatter
    k_init<<<(N + 255) / 256, 256>>>(N);
    k_gi_enc<<<(DIM3 + 7) / 8, 256>>>(enc, W_ih, b_ih);

    // sub = tanh(mask @ W_sub^T + b_sub)                [S, 768]
    gemm_nt<1><<<dim3(DIM / 128, (S + 127) / 128), 256>>>(smask, W_sub, b_sub, p_sub, S, DIM, DIM);
    // gh = sub @ W_hh^T + b_hh                          [S, 2304]
    gemm_nt<0><<<dim3(DIM3 / 128, (S + 127) / 128), 256>>>(p_sub, W_hh, b_hh, p_gh, S, DIM3, DIM);
    // r0 = GRU(enc, sub)
    k_gru_r0<<<(S * DIM + 255) / 256, 256>>>(S);
    // gi0 = r0 @ W_ih^T + b_ih                          [S, 2304]
    gemm_nt<0><<<dim3(DIM3 / 128, (S + 127) / 128), 256>>>(p_r0, W_ih, b_ih, p_gi0, S, DIM3, DIM);
    // ghR = rel_emb @ W_hh^T + b_hh                     [R, 2304]
    gemm_nt<0><<<dim3(DIM3 / 128, (R + 127) / 128), 256>>>(relE, W_hh, b_hh, p_ghR, R, DIM3, DIM);

    k_seed<<<(S + 255) / 256, 256>>>(seeds, S, stride);
    k_edge<<<(E + 255) / 256, 256>>>(ehead, etail, E, stride);

    // rj[e] = GRU(gi0[head[e]], rel[type[e]])           [E, 768]
    k_rj<<<E, 192>>>(ehead, etype, relE);
    // obj = tanh(rj @ W_obj^T + b_obj)                  [E, 768]  -- dominant GEMM
    gemm_nt<1><<<dim3(DIM / 128, (E + 127) / 128), 256>>>(p_rj, W_obj, b_obj, p_obj, E, DIM, DIM);

    // gather winners / defaults into output
    k_out<<<N, 192>>>(n2n, oldnd, defa, out, stride);
}

// round 7
// speedup vs baseline: 2.1035x; 2.1035x over previous
#include <cuda_runtime.h>
#include <cuda_bf16.h>
#include <stdint.h>

#define DIM  768
#define DIM2 1536
#define DIM3 2304
#define MAX_S 2048
#define MAX_E 32768
#define MAX_N 100000
#define MAX_R 1000

// ---------------- fp32 scratch ----------------
__device__ float g_sub [MAX_S * DIM];
__device__ float g_gh  [MAX_S * DIM3];
__device__ float g_gi0 [MAX_S * DIM3];
__device__ float g_ghR [MAX_R * DIM3];
__device__ float g_obj [MAX_E * DIM];
__device__ float g_gi_enc[DIM3];
__device__ int   g_best[MAX_N];
__device__ int   g_seedpos[MAX_N];

// ---------------- bf16 split scratch: [rows][1536], hi in [0,768), lo in [768,1536) ----
__device__ __nv_bfloat16 g_smasks[MAX_S * DIM2];
__device__ __nv_bfloat16 g_subs  [MAX_S * DIM2];
__device__ __nv_bfloat16 g_r0s   [MAX_S * DIM2];
__device__ __nv_bfloat16 g_rjs   [(size_t)MAX_E * DIM2];
__device__ __nv_bfloat16 g_rels  [MAX_R * DIM2];
__device__ __nv_bfloat16 g_Wsubs [DIM  * DIM2];
__device__ __nv_bfloat16 g_Wobjs [DIM  * DIM2];
__device__ __nv_bfloat16 g_Wihs  [DIM3 * DIM2];
__device__ __nv_bfloat16 g_Whhs  [DIM3 * DIM2];

// ---------------- helpers ----------------
__device__ __forceinline__ uint32_t smem_u32(const void* p) {
    uint32_t a;
    asm("{ .reg .u64 t; cvta.to.shared.u64 t, %1; cvt.u32.u64 %0, t; }" : "=r"(a) : "l"(p));
    return a;
}

union BQ { __nv_bfloat16 b[4]; uint2 u; };
__device__ __forceinline__ void split4(float4 v, uint2& hi, uint2& lo) {
    BQ H, L;
    H.b[0] = __float2bfloat16_rn(v.x); L.b[0] = __float2bfloat16_rn(v.x - __bfloat162float(H.b[0]));
    H.b[1] = __float2bfloat16_rn(v.y); L.b[1] = __float2bfloat16_rn(v.y - __bfloat162float(H.b[1]));
    H.b[2] = __float2bfloat16_rn(v.z); L.b[2] = __float2bfloat16_rn(v.z - __bfloat162float(H.b[2]));
    H.b[3] = __float2bfloat16_rn(v.w); L.b[3] = __float2bfloat16_rn(v.w - __bfloat162float(H.b[3]));
    hi = H.u; lo = L.u;
}
union BP { __nv_bfloat16 b[2]; uint32_t u; };
__device__ __forceinline__ void split2(float x0, float x1, uint32_t& hi, uint32_t& lo) {
    BP H, L;
    H.b[0] = __float2bfloat16_rn(x0); L.b[0] = __float2bfloat16_rn(x0 - __bfloat162float(H.b[0]));
    H.b[1] = __float2bfloat16_rn(x1); L.b[1] = __float2bfloat16_rn(x1 - __bfloat162float(H.b[1]));
    hi = H.u; lo = L.u;
}

#define LDSM_X4(r0, r1, r2, r3, addr) \
    asm volatile("ldmatrix.sync.aligned.m8n8.x4.shared.b16 {%0,%1,%2,%3}, [%4];" \
        : "=r"(r0), "=r"(r1), "=r"(r2), "=r"(r3) : "r"(addr))

#define MMA_BF16(d, a, b0v, b1v) \
    asm volatile("mma.sync.aligned.m16n8k16.row.col.f32.bf16.bf16.f32 " \
        "{%0,%1,%2,%3}, {%4,%5,%6,%7}, {%8,%9}, {%0,%1,%2,%3};" \
        : "+f"((d)[0]), "+f"((d)[1]), "+f"((d)[2]), "+f"((d)[3]) \
        : "r"((a)[0]), "r"((a)[1]), "r"((a)[2]), "r"((a)[3]), "r"(b0v), "r"(b1v))

#define CP_ASYNC16(dst, src) \
    asm volatile("cp.async.cg.shared.global [%0], [%1], 16;" :: "r"(dst), "l"(src))
#define CP_COMMIT()  asm volatile("cp.async.commit_group;" ::: "memory")
#define CP_WAIT1()   asm volatile("cp.async.wait_group 1;" ::: "memory")

// ================= tensor-core GEMM (mma.sync bf16, split-3x fp32 emulation) =========
// C[M,N] = act(Ahl @ Whl^T + bias). Ahl/Whl: split-bf16 [rows][1536], K=768.
// Virtual K = 2304 over 3 phases: (A hi, W hi), (A lo, W hi), (A hi, W lo).
// Tile 128x128, BK=64, 256 thr (8 warps, 4m x 2n, warp tile 32x64), 3-stage cp.async.
#define STAGES 3
#define STG_BYTES 32768
#define GEMM_SMEM (STAGES * STG_BYTES + 128)

template<int ACT, int SPLIT>
__global__ __launch_bounds__(256, 2)
void gemm_tc(const __nv_bfloat16* __restrict__ A, const __nv_bfloat16* __restrict__ W,
             const float* __restrict__ bias, float* __restrict__ C,
             __nv_bfloat16* __restrict__ Cs, int M, int N)
{
    extern __shared__ char smraw[];
    const uint32_t sbase = (smem_u32(smraw) + 127u) & ~127u;

    const int tid  = threadIdx.x;
    const int lane = tid & 31;
    const int wid  = tid >> 5;
    const int wm   = wid & 3;          // 0..3  -> m offset 32*wm
    const int wn   = wid >> 2;         // 0..1  -> n offset 64*wn
    const int row0 = blockIdx.y * 128;
    const int col0 = blockIdx.x * 128;

    // ---- loader precompute: thread covers row tid/2, 64B half (tid&1) ----
    const int lrow  = tid >> 1;
    const int lhalf = tid & 1;
    const int arow  = min(row0 + lrow, M - 1);      // clamp: extra rows never stored
    const __nv_bfloat16* gA = A + (size_t)arow * DIM2;
    const __nv_bfloat16* gB = W + (size_t)(col0 + lrow) * DIM2;
    uint32_t sdst[4];
    {
        const uint32_t rb = (uint32_t)lrow * 128u;
        const uint32_t xv = ((uint32_t)lrow & 7u) << 4;
#pragma unroll
        for (int i = 0; i < 4; i++)
            sdst[i] = rb + ((((uint32_t)lhalf) * 64u + (uint32_t)i * 16u) ^ xv);
    }

    // ---- ldmatrix per-lane precompute ----
    const int l8 = lane & 7;
    const int mi = lane >> 3;          // matrix index within x4
    uint32_t aoff[2], ax[2];
#pragma unroll
    for (int s = 0; s < 2; s++) {
        int r = wm * 32 + s * 16 + (mi & 1) * 8 + l8;
        aoff[s] = (uint32_t)r * 128u;
        ax[s]   = ((uint32_t)r & 7u) << 4;
    }
    const uint32_t akb = (uint32_t)(mi >> 1) * 16u;
    uint32_t boff[4], bx[4];
#pragma unroll
    for (int j = 0; j < 4; j++) {
        int r = wn * 64 + j * 16 + (mi >> 1) * 8 + l8;
        boff[j] = (uint32_t)r * 128u;
        bx[j]   = ((uint32_t)r & 7u) << 4;
    }
    const uint32_t bkb = (uint32_t)(mi & 1) * 16u;

    float acc[2][8][4];
#pragma unroll
    for (int s = 0; s < 2; s++)
#pragma unroll
        for (int j = 0; j < 8; j++)
#pragma unroll
            for (int q = 0; q < 4; q++) acc[s][j][q] = 0.f;

    // ---- stage issue ----
    auto issue = [&](int c) {
        const int p  = c / 12;
        const int kc = c - p * 12;
        const int acol = ((p == 1) ? DIM : 0) + kc * 64 + lhalf * 32;
        const int bcol = ((p == 2) ? DIM : 0) + kc * 64 + lhalf * 32;
        const uint32_t Ab = sbase + (uint32_t)(c % STAGES) * STG_BYTES;
        const uint32_t Bb = Ab + 16384u;
        const __nv_bfloat16* pa = gA + acol;
        const __nv_bfloat16* pb = gB + bcol;
#pragma unroll
        for (int i = 0; i < 4; i++) CP_ASYNC16(Ab + sdst[i], pa + i * 8);
#pragma unroll
        for (int i = 0; i < 4; i++) CP_ASYNC16(Bb + sdst[i], pb + i * 8);
        CP_COMMIT();
    };

    issue(0);
    issue(1);

    for (int c = 0; c < 36; c++) {
        CP_WAIT1();
        __syncthreads();
        const uint32_t Ab = sbase + (uint32_t)(c % STAGES) * STG_BYTES;
        const uint32_t Bb = Ab + 16384u;
#pragma unroll
        for (int kk = 0; kk < 4; kk++) {
            const uint32_t kb = (uint32_t)kk * 32u;
            uint32_t a[2][4];
#pragma unroll
            for (int s = 0; s < 2; s++) {
                uint32_t ad = Ab + aoff[s] + ((kb + akb) ^ ax[s]);
                LDSM_X4(a[s][0], a[s][1], a[s][2], a[s][3], ad);
            }
#pragma unroll
            for (int j = 0; j < 4; j++) {
                uint32_t b[4];
                uint32_t bd = Bb + boff[j] + ((kb + bkb) ^ bx[j]);
                LDSM_X4(b[0], b[1], b[2], b[3], bd);
                MMA_BF16(acc[0][2 * j],     a[0], b[0], b[1]);
                MMA_BF16(acc[0][2 * j + 1], a[0], b[2], b[3]);
                MMA_BF16(acc[1][2 * j],     a[1], b[0], b[1]);
                MMA_BF16(acc[1][2 * j + 1], a[1], b[2], b[3]);
            }
        }
        if (c + 2 < 36) issue(c + 2);
    }

    // ---- epilogue ----
    const int mrow = lane >> 2;
    const int mcol = (lane & 3) * 2;
#pragma unroll
    for (int s = 0; s < 2; s++) {
        const int r1 = row0 + wm * 32 + s * 16 + mrow;
        const int r2 = r1 + 8;
#pragma unroll
        for (int j = 0; j < 8; j++) {
            const int col = col0 + wn * 64 + j * 8 + mcol;
            const float b0v = bias[col], b1v = bias[col + 1];
            float x0 = acc[s][j][0] + b0v, x1 = acc[s][j][1] + b1v;
            float y0 = acc[s][j][2] + b0v, y1 = acc[s][j][3] + b1v;
            if (ACT) { x0 = tanhf(x0); x1 = tanhf(x1); y0 = tanhf(y0); y1 = tanhf(y1); }
            if (r1 < M) {
                float2 v = make_float2(x0, x1);
                *(float2*)(C + (size_t)r1 * N + col) = v;
                if (SPLIT) {
                    uint32_t hi, lo; split2(x0, x1, hi, lo);
                    __nv_bfloat16* hrow = Cs + (size_t)r1 * DIM2;
                    *(uint32_t*)(hrow + col)       = hi;
                    *(uint32_t*)(hrow + DIM + col) = lo;
                }
            }
            if (r2 < M) {
                float2 v = make_float2(y0, y1);
                *(float2*)(C + (size_t)r2 * N + col) = v;
                if (SPLIT) {
                    uint32_t hi, lo; split2(y0, y1, hi, lo);
                    __nv_bfloat16* hrow = Cs + (size_t)r2 * DIM2;
                    *(uint32_t*)(hrow + col)       = hi;
                    *(uint32_t*)(hrow + DIM + col) = lo;
                }
            }
        }
    }
}

// ================= elementwise / scatter kernels =================
__global__ void k_split(const float* __restrict__ X, __nv_bfloat16* __restrict__ Y, int total4)
{
    int i = blockIdx.x * blockDim.x + threadIdx.x;
    if (i >= total4) return;
    int r = i / 192, c = (i - r * 192) * 4;
    float4 v = *(const float4*)(X + (size_t)r * DIM + c);
    uint2 hi, lo; split4(v, hi, lo);
    __nv_bfloat16* row = Y + (size_t)r * DIM2;
    *(uint2*)(row + c)       = hi;
    *(uint2*)(row + DIM + c) = lo;
}

__global__ void k_gi_enc(const float* __restrict__ enc, const float* __restrict__ W_ih,
                         const float* __restrict__ b_ih)
{
    int j = blockIdx.x * 8 + (threadIdx.x >> 5);
    int lane = threadIdx.x & 31;
    if (j >= DIM3) return;
    const float* w = W_ih + (size_t)j * DIM;
    float s = 0.f;
#pragma unroll
    for (int k = lane * 4; k < DIM; k += 128) {
        float4 wv = *(const float4*)(w + k);
        float4 ev = *(const float4*)(enc + k);
        s += wv.x * ev.x + wv.y * ev.y + wv.z * ev.z + wv.w * ev.w;
    }
#pragma unroll
    for (int o = 16; o; o >>= 1) s += __shfl_xor_sync(0xffffffffu, s, o);
    if (lane == 0) g_gi_enc[j] = s + b_ih[j];
}

__device__ __forceinline__ float sigm(float x) { return 1.f / (1.f + __expf(-x)); }
__device__ __forceinline__ float gru1(float ir, float iz, float in_,
                                      float hr, float hz, float hn, float h) {
    float r = sigm(ir + hr);
    float z = sigm(iz + hz);
    float n = tanhf(in_ + r * hn);
    return (1.f - z) * n + z * h;
}

// r0 = GRU(enc broadcast, h=sub) -> split bf16 (consumed only by gi0 GEMM)
__global__ void k_gru_r0(int S)
{
    int i = blockIdx.x * blockDim.x + threadIdx.x;
    if (i >= S * 192) return;
    int s = i / 192, d = (i - s * 192) * 4;
    const float* gh = g_gh + (size_t)s * DIM3;
    float4 ir  = *(const float4*)(g_gi_enc + d);
    float4 iz  = *(const float4*)(g_gi_enc + DIM + d);
    float4 in_ = *(const float4*)(g_gi_enc + 2 * DIM + d);
    float4 hr  = *(const float4*)(gh + d);
    float4 hz  = *(const float4*)(gh + DIM + d);
    float4 hn  = *(const float4*)(gh + 2 * DIM + d);
    float4 hh  = *(const float4*)(g_sub + (size_t)s * DIM + d);
    float4 o;
    o.x = gru1(ir.x, iz.x, in_.x, hr.x, hz.x, hn.x, hh.x);
    o.y = gru1(ir.y, iz.y, in_.y, hr.y, hz.y, hn.y, hh.y);
    o.z = gru1(ir.z, iz.z, in_.z, hr.z, hz.z, hn.z, hh.z);
    o.w = gru1(ir.w, iz.w, in_.w, hr.w, hz.w, hn.w, hh.w);
    uint2 hi, lo; split4(o, hi, lo);
    __nv_bfloat16* row = g_r0s + (size_t)s * DIM2;
    *(uint2*)(row + d)       = hi;
    *(uint2*)(row + DIM + d) = lo;
}

__global__ void k_init(int N)
{
    int i = blockIdx.x * blockDim.x + threadIdx.x;
    if (i < N) { g_best[i] = -1; g_seedpos[i] = -1; }
}
__global__ void k_seed(const int* __restrict__ seeds, int S, int stride)
{
    int s = blockIdx.x * blockDim.x + threadIdx.x;
    if (s >= S) return;
    int node = seeds[s];
    g_seedpos[node] = s;
    atomicMax(&g_best[node], s * stride);
}
__global__ void k_edge(const int* __restrict__ heads, const int* __restrict__ tails,
                       int E, int stride)
{
    int e = blockIdx.x * blockDim.x + threadIdx.x;
    if (e >= E) return;
    int pos = g_seedpos[heads[e]];
    int t = pos * stride + 1 + e;
    atomicMax(&g_best[tails[e]], t);
}

// rj[e] = GRU(gi0[head], ghR[type], h=rel[type]) -> split bf16
__global__ void k_rj(const int* __restrict__ heads, const int* __restrict__ types,
                     const float* __restrict__ rel)
{
    int e = blockIdx.x;
    int h = heads[e];
    int t = types[e];
    const float* gi = g_gi0 + (size_t)h * DIM3;
    const float* gh = g_ghR + (size_t)t * DIM3;
    const float* rl = rel + (size_t)t * DIM;
    int d = threadIdx.x * 4;
    float4 ir  = *(const float4*)(gi + d);
    float4 iz  = *(const float4*)(gi + DIM + d);
    float4 in_ = *(const float4*)(gi + 2 * DIM + d);
    float4 hr  = *(const float4*)(gh + d);
    float4 hz  = *(const float4*)(gh + DIM + d);
    float4 hn  = *(const float4*)(gh + 2 * DIM + d);
    float4 hh  = *(const float4*)(rl + d);
    float4 o;
    o.x = gru1(ir.x, iz.x, in_.x, hr.x, hz.x, hn.x, hh.x);
    o.y = gru1(ir.y, iz.y, in_.y, hr.y, hz.y, hn.y, hh.y);
    o.z = gru1(ir.z, iz.z, in_.z, hr.z, hz.z, hn.z, hh.z);
    o.w = gru1(ir.w, iz.w, in_.w, hr.w, hz.w, hn.w, hh.w);
    uint2 hi, lo; split4(o, hi, lo);
    __nv_bfloat16* row = g_rjs + (size_t)e * DIM2;
    *(uint2*)(row + d)       = hi;
    *(uint2*)(row + DIM + d) = lo;
}

__global__ void k_out(const int* __restrict__ node2node, const int* __restrict__ old_nd,
                      const float* __restrict__ defa, float* __restrict__ out, int stride)
{
    int nrow = blockIdx.x;
    int id = node2node[old_nd[nrow]];
    int b = g_best[id];
    const float* src;
    if (b < 0) {
        src = defa + (size_t)nrow * DIM;
    } else {
        int q = b / stride;
        int rem = b - q * stride;
        src = (rem == 0) ? (g_sub + (size_t)q * DIM)
                         : (g_obj + (size_t)(rem - 1) * DIM);
    }
    int d = threadIdx.x * 4;
    *(float4*)(out + (size_t)nrow * DIM + d) = *(const float4*)(src + d);
}

// ================= host =================
extern "C" void kernel_launch(void* const* d_in, const int* in_sizes, int n_in,
                              void* d_out, int out_size)
{
    const float* enc   = (const float*)d_in[0];
    const float* smask = (const float*)d_in[1];
    const int*   seeds = (const int*)  d_in[2];
    const int*   ehead = (const int*)  d_in[3];
    const int*   etail = (const int*)  d_in[4];
    const int*   etype = (const int*)  d_in[5];
    const int*   n2n   = (const int*)  d_in[6];
    const int*   oldnd = (const int*)  d_in[7];
    const float* relE  = (const float*)d_in[8];
    const float* W_sub = (const float*)d_in[9];
    const float* b_sub = (const float*)d_in[10];
    const float* W_obj = (const float*)d_in[11];
    const float* b_obj = (const float*)d_in[12];
    const float* W_ih  = (const float*)d_in[13];
    const float* W_hh  = (const float*)d_in[14];
    const float* b_ih  = (const float*)d_in[15];
    const float* b_hh  = (const float*)d_in[16];
    const float* defa  = (const float*)d_in[17];
    float* out = (float*)d_out;

    const int S = in_sizes[2];
    const int E = in_sizes[3];
    const int N = in_sizes[6];
    const int R = in_sizes[8] / DIM;
    const int stride = E + 1;

    float *p_sub, *p_gh, *p_gi0, *p_ghR, *p_obj;
    __nv_bfloat16 *p_smasks, *p_subs, *p_r0s, *p_rjs, *p_rels,
                  *p_Wsubs, *p_Wobjs, *p_Wihs, *p_Whhs;
    cudaGetSymbolAddress((void**)&p_sub,    g_sub);
    cudaGetSymbolAddress((void**)&p_gh,     g_gh);
    cudaGetSymbolAddress((void**)&p_gi0,    g_gi0);
    cudaGetSymbolAddress((void**)&p_ghR,    g_ghR);
    cudaGetSymbolAddress((void**)&p_obj,    g_obj);
    cudaGetSymbolAddress((void**)&p_smasks, g_smasks);
    cudaGetSymbolAddress((void**)&p_subs,   g_subs);
    cudaGetSymbolAddress((void**)&p_r0s,    g_r0s);
    cudaGetSymbolAddress((void**)&p_rjs,    g_rjs);
    cudaGetSymbolAddress((void**)&p_rels,   g_rels);
    cudaGetSymbolAddress((void**)&p_Wsubs,  g_Wsubs);
    cudaGetSymbolAddress((void**)&p_Wobjs,  g_Wobjs);
    cudaGetSymbolAddress((void**)&p_Wihs,   g_Wihs);
    cudaGetSymbolAddress((void**)&p_Whhs,   g_Whhs);

    cudaFuncSetAttribute(gemm_tc<1,1>, cudaFuncAttributeMaxDynamicSharedMemorySize, GEMM_SMEM);
    cudaFuncSetAttribute(gemm_tc<0,0>, cudaFuncAttributeMaxDynamicSharedMemorySize, GEMM_SMEM);
    cudaFuncSetAttribute(gemm_tc<1,0>, cudaFuncAttributeMaxDynamicSharedMemorySize, GEMM_SMEM);

    k_init<<<(N + 255) / 256, 256>>>(N);

    // split fp32 inputs into (hi,lo) bf16 pairs
    k_split<<<(S * 192 + 255) / 256, 256>>>(smask, p_smasks, S * 192);
    k_split<<<(DIM * 192 + 255) / 256, 256>>>(W_sub, p_Wsubs, DIM * 192);
    k_split<<<(DIM * 192 + 255) / 256, 256>>>(W_obj, p_Wobjs, DIM * 192);
    k_split<<<(DIM3 * 192 + 255) / 256, 256>>>(W_ih, p_Wihs, DIM3 * 192);
    k_split<<<(DIM3 * 192 + 255) / 256, 256>>>(W_hh, p_Whhs, DIM3 * 192);
    k_split<<<(R * 192 + 255) / 256, 256>>>(relE, p_rels, R * 192);

    k_gi_enc<<<(DIM3 + 7) / 8, 256>>>(enc, W_ih, b_ih);

    // sub = tanh(mask @ W_sub^T + b_sub)      [S,768], + split copy
    gemm_tc<1,1><<<dim3(DIM / 128, S / 128), 256, GEMM_SMEM>>>(
        p_smasks, p_Wsubs, b_sub, p_sub, p_subs, S, DIM);
    // gh = sub @ W_hh^T + b_hh                [S,2304]
    gemm_tc<0,0><<<dim3(DIM3 / 128, S / 128), 256, GEMM_SMEM>>>(
        p_subs, p_Whhs, b_hh, p_gh, (__nv_bfloat16*)0, S, DIM3);
    // r0 = GRU(enc, sub) -> split bf16
    k_gru_r0<<<(S * 192 + 255) / 256, 256>>>(S);
    // gi0 = r0 @ W_ih^T + b_ih                [S,2304]
    gemm_tc<0,0><<<dim3(DIM3 / 128, S / 128), 256, GEMM_SMEM>>>(
        p_r0s, p_Wihs, b_ih, p_gi0, (__nv_bfloat16*)0, S, DIM3);
    // ghR = rel_emb @ W_hh^T + b_hh           [R,2304]
    gemm_tc<0,0><<<dim3(DIM3 / 128, (R + 127) / 128), 256, GEMM_SMEM>>>(
        p_rels, p_Whhs, b_hh, p_ghR, (__nv_bfloat16*)0, R, DIM3);

    k_seed<<<(S + 255) / 256, 256>>>(seeds, S, stride);
    k_edge<<<(E + 255) / 256, 256>>>(ehead, etail, E, stride);

    // rj[e] = GRU(gi0[head], rel[type]) -> split bf16
    k_rj<<<E, 192>>>(ehead, etype, relE);
    // obj = tanh(rj @ W_obj^T + b_obj)        [E,768]  (dominant GEMM)
    gemm_tc<1,0><<<dim3(DIM / 128, E / 128), 256, GEMM_SMEM>>>(
        p_rjs, p_Wobjs, b_obj, p_obj, (__nv_bfloat16*)0, E, DIM);

    k_out<<<N, 192>>>(n2n, oldnd, defa, out, stride);
}

// round 10
// speedup vs baseline: 2.6944x; 1.2809x over previous
#include <cuda_runtime.h>
#include <cuda_fp16.h>
#include <stdint.h>

#define DIM  768
#define DIM2 1536
#define DIM3 2304
#define MAX_S 2048
#define MAX_E 32768
#define MAX_N 100000
#define MAX_R 1000

// ---------------- fp32 scratch ----------------
__device__ float g_sub [MAX_S * DIM];
__device__ float g_gh  [MAX_S * DIM3];
__device__ float g_gi0 [MAX_S * DIM3];
__device__ float g_ghR [MAX_R * DIM3];
__device__ float g_obj [MAX_E * DIM];
__device__ float g_gi_enc[DIM3];
__device__ int   g_best[MAX_N];
__device__ int   g_seedpos[MAX_N];

// ---- fp16 A-operand scratch: [rows][1536], hi in [0,768), lo in [768,1536) ----
__device__ __half g_smasks[MAX_S * DIM2];
__device__ __half g_subs  [MAX_S * DIM2];
__device__ __half g_r0s   [MAX_S * DIM2];
__device__ __half g_rjs   [(size_t)MAX_E * DIM2];
__device__ __half g_rels  [MAX_R * DIM2];
// ---- fp16 W-operand scratch (hi only): [rows][768] ----
__device__ __half g_Wsubs [DIM  * DIM];
__device__ __half g_Wobjs [DIM  * DIM];
__device__ __half g_Wihs  [DIM3 * DIM];
__device__ __half g_Whhs  [DIM3 * DIM];

// ---------------- helpers ----------------
__device__ __forceinline__ uint32_t smem_u32(const void* p) {
    uint32_t a;
    asm("{ .reg .u64 t; cvta.to.shared.u64 t, %1; cvt.u32.u64 %0, t; }" : "=r"(a) : "l"(p));
    return a;
}

union HQ { __half h[4]; uint2 u; };
__device__ __forceinline__ void split4(float4 v, uint2& hi, uint2& lo) {
    HQ H, L;
    H.h[0] = __float2half_rn(v.x); L.h[0] = __float2half_rn(v.x - __half2float(H.h[0]));
    H.h[1] = __float2half_rn(v.y); L.h[1] = __float2half_rn(v.y - __half2float(H.h[1]));
    H.h[2] = __float2half_rn(v.z); L.h[2] = __float2half_rn(v.z - __half2float(H.h[2]));
    H.h[3] = __float2half_rn(v.w); L.h[3] = __float2half_rn(v.w - __half2float(H.h[3]));
    hi = H.u; lo = L.u;
}
union HP { __half h[2]; uint32_t u; };
__device__ __forceinline__ void split2(float x0, float x1, uint32_t& hi, uint32_t& lo) {
    HP H, L;
    H.h[0] = __float2half_rn(x0); L.h[0] = __float2half_rn(x0 - __half2float(H.h[0]));
    H.h[1] = __float2half_rn(x1); L.h[1] = __float2half_rn(x1 - __half2float(H.h[1]));
    hi = H.u; lo = L.u;
}

#define LDSM_X4(r0, r1, r2, r3, addr) \
    asm volatile("ldmatrix.sync.aligned.m8n8.x4.shared.b16 {%0,%1,%2,%3}, [%4];" \
        : "=r"(r0), "=r"(r1), "=r"(r2), "=r"(r3) : "r"(addr))

#define MMA_F16(d, a, b0v, b1v) \
    asm volatile("mma.sync.aligned.m16n8k16.row.col.f32.f16.f16.f32 " \
        "{%0,%1,%2,%3}, {%4,%5,%6,%7}, {%8,%9}, {%0,%1,%2,%3};" \
        : "+f"((d)[0]), "+f"((d)[1]), "+f"((d)[2]), "+f"((d)[3]) \
        : "r"((a)[0]), "r"((a)[1]), "r"((a)[2]), "r"((a)[3]), "r"(b0v), "r"(b1v))

#define CP_ASYNC16(dst, src) \
    asm volatile("cp.async.cg.shared.global [%0], [%1], 16;" :: "r"(dst), "l"(src))
#define CP_COMMIT()  asm volatile("cp.async.commit_group;" ::: "memory")
#define CP_WAIT1()   asm volatile("cp.async.wait_group 1;" ::: "memory")

// ================= tensor-core GEMM (mma.sync fp16, 2-term split) =========
// C[M,N] = act(A @ W^T + bias). A: fp16 split [rows][1536] (hi|lo), W: fp16 hi [rows][768].
// Virtual K = 1536 over 2 phases: (A_hi, W_hi), (A_lo, W_hi). fp32 accumulate.
// Tile 128x128, BK=64, 256 thr (8 warps, 4m x 2n, warp tile 32x64), 3-stage cp.async.
#define STAGES 3
#define STG_BYTES 32768
#define GEMM_SMEM (STAGES * STG_BYTES + 128)
#define NCHUNK 24

template<int ACT, int SPLIT>
__global__ __launch_bounds__(256, 2)
void gemm_tc(const __half* __restrict__ A, const __half* __restrict__ W,
             const float* __restrict__ bias, float* __restrict__ C,
             __half* __restrict__ Cs, int M, int N)
{
    extern __shared__ char smraw[];
    const uint32_t sbase = (smem_u32(smraw) + 127u) & ~127u;

    const int tid  = threadIdx.x;
    const int lane = tid & 31;
    const int wid  = tid >> 5;
    const int wm   = wid & 3;          // m offset 32*wm
    const int wn   = wid >> 2;         // n offset 64*wn
    const int row0 = blockIdx.y * 128;
    const int col0 = blockIdx.x * 128;

    // ---- loader precompute: thread covers row tid/2, 64B half (tid&1) ----
    const int lrow  = tid >> 1;
    const int lhalf = tid & 1;
    const int arow  = min(row0 + lrow, M - 1);      // clamp: extra rows never stored
    const __half* gA = A + (size_t)arow * DIM2;
    const __half* gB = W + (size_t)(col0 + lrow) * DIM;
    uint32_t sdst[4];
    {
        const uint32_t rb = (uint32_t)lrow * 128u;
        const uint32_t xv = ((uint32_t)lrow & 7u) << 4;
#pragma unroll
        for (int i = 0; i < 4; i++)
            sdst[i] = rb + ((((uint32_t)lhalf) * 64u + (uint32_t)i * 16u) ^ xv);
    }

    // ---- ldmatrix per-lane precompute ----
    const int l8 = lane & 7;
    const int mi = lane >> 3;
    uint32_t aoff[2], ax[2];
#pragma unroll
    for (int s = 0; s < 2; s++) {
        int r = wm * 32 + s * 16 + (mi & 1) * 8 + l8;
        aoff[s] = (uint32_t)r * 128u;
        ax[s]   = ((uint32_t)r & 7u) << 4;
    }
    const uint32_t akb = (uint32_t)(mi >> 1) * 16u;
    uint32_t boff[4], bx[4];
#pragma unroll
    for (int j = 0; j < 4; j++) {
        int r = wn * 64 + j * 16 + (mi >> 1) * 8 + l8;
        boff[j] = (uint32_t)r * 128u;
        bx[j]   = ((uint32_t)r & 7u) << 4;
    }
    const uint32_t bkb = (uint32_t)(mi & 1) * 16u;

    float acc[2][8][4];
#pragma unroll
    for (int s = 0; s < 2; s++)
#pragma unroll
        for (int j = 0; j < 8; j++)
#pragma unroll
            for (int q = 0; q < 4; q++) acc[s][j][q] = 0.f;

    // ---- stage issue: chunk c -> phase p=c/12 (A hi/lo), kc=c%12 ----
    auto issue = [&](int c) {
        const int p  = c / 12;
        const int kc = c - p * 12;
        const int acol = p * DIM + kc * 64 + lhalf * 32;
        const int bcol = kc * 64 + lhalf * 32;
        const uint32_t Ab = sbase + (uint32_t)(c % STAGES) * STG_BYTES;
        const uint32_t Bb = Ab + 16384u;
        const __half* pa = gA + acol;
        const __half* pb = gB + bcol;
#pragma unroll
        for (int i = 0; i < 4; i++) CP_ASYNC16(Ab + sdst[i], pa + i * 8);
#pragma unroll
        for (int i = 0; i < 4; i++) CP_ASYNC16(Bb + sdst[i], pb + i * 8);
        CP_COMMIT();
    };

    issue(0);
    issue(1);

    for (int c = 0; c < NCHUNK; c++) {
        CP_WAIT1();
        __syncthreads();
        const uint32_t Ab = sbase + (uint32_t)(c % STAGES) * STG_BYTES;
        const uint32_t Bb = Ab + 16384u;
#pragma unroll
        for (int kk = 0; kk < 4; kk++) {
            const uint32_t kb = (uint32_t)kk * 32u;
            uint32_t a[2][4];
#pragma unroll
            for (int s = 0; s < 2; s++) {
                uint32_t ad = Ab + aoff[s] + ((kb + akb) ^ ax[s]);
                LDSM_X4(a[s][0], a[s][1], a[s][2], a[s][3], ad);
            }
#pragma unroll
            for (int j = 0; j < 4; j++) {
                uint32_t b[4];
                uint32_t bd = Bb + boff[j] + ((kb + bkb) ^ bx[j]);
                LDSM_X4(b[0], b[1], b[2], b[3], bd);
                MMA_F16(acc[0][2 * j],     a[0], b[0], b[1]);
                MMA_F16(acc[0][2 * j + 1], a[0], b[2], b[3]);
                MMA_F16(acc[1][2 * j],     a[1], b[0], b[1]);
                MMA_F16(acc[1][2 * j + 1], a[1], b[2], b[3]);
            }
        }
        if (c + 2 < NCHUNK) issue(c + 2);
    }

    // ---- epilogue ----
    const int mrow = lane >> 2;
    const int mcol = (lane & 3) * 2;
#pragma unroll
    for (int s = 0; s < 2; s++) {
        const int r1 = row0 + wm * 32 + s * 16 + mrow;
        const int r2 = r1 + 8;
#pragma unroll
        for (int j = 0; j < 8; j++) {
            const int col = col0 + wn * 64 + j * 8 + mcol;
            const float b0v = bias[col], b1v = bias[col + 1];
            float x0 = acc[s][j][0] + b0v, x1 = acc[s][j][1] + b1v;
            float y0 = acc[s][j][2] + b0v, y1 = acc[s][j][3] + b1v;
            if (ACT) { x0 = tanhf(x0); x1 = tanhf(x1); y0 = tanhf(y0); y1 = tanhf(y1); }
            if (r1 < M) {
                *(float2*)(C + (size_t)r1 * N + col) = make_float2(x0, x1);
                if (SPLIT) {
                    uint32_t hi, lo; split2(x0, x1, hi, lo);
                    __half* hrow = Cs + (size_t)r1 * DIM2;
                    *(uint32_t*)(hrow + col)       = hi;
                    *(uint32_t*)(hrow + DIM + col) = lo;
                }
            }
            if (r2 < M) {
                *(float2*)(C + (size_t)r2 * N + col) = make_float2(y0, y1);
                if (SPLIT) {
                    uint32_t hi, lo; split2(y0, y1, hi, lo);
                    __half* hrow = Cs + (size_t)r2 * DIM2;
                    *(uint32_t*)(hrow + col)       = hi;
                    *(uint32_t*)(hrow + DIM + col) = lo;
                }
            }
        }
    }
}

// ================= elementwise / scatter kernels =================
// A-operand split: fp32 [rows][768] -> fp16 [rows][1536] (hi|lo)
__global__ void k_split(const float* __restrict__ X, __half* __restrict__ Y, int total4)
{
    int i = blockIdx.x * blockDim.x + threadIdx.x;
    if (i >= total4) return;
    int r = i / 192, c = (i - r * 192) * 4;
    float4 v = *(const float4*)(X + (size_t)r * DIM + c);
    uint2 hi, lo; split4(v, hi, lo);
    __half* row = Y + (size_t)r * DIM2;
    *(uint2*)(row + c)       = hi;
    *(uint2*)(row + DIM + c) = lo;
}
// W-operand: fp32 -> fp16 hi only, same [rows][768] layout
__global__ void k_half(const float* __restrict__ X, __half* __restrict__ Y, int total4)
{
    int i = blockIdx.x * blockDim.x + threadIdx.x;
    if (i >= total4) return;
    float4 v = *(const float4*)(X + (size_t)i * 4);
    HQ H;
    H.h[0] = __float2half_rn(v.x); H.h[1] = __float2half_rn(v.y);
    H.h[2] = __float2half_rn(v.z); H.h[3] = __float2half_rn(v.w);
    *(uint2*)(Y + (size_t)i * 4) = H.u;
}

__global__ void k_gi_enc(const float* __restrict__ enc, const float* __restrict__ W_ih,
                         const float* __restrict__ b_ih)
{
    int j = blockIdx.x * 8 + (threadIdx.x >> 5);
    int lane = threadIdx.x & 31;
    if (j >= DIM3) return;
    const float* w = W_ih + (size_t)j * DIM;
    float s = 0.f;
#pragma unroll
    for (int k = lane * 4; k < DIM; k += 128) {
        float4 wv = *(const float4*)(w + k);
        float4 ev = *(const float4*)(enc + k);
        s += wv.x * ev.x + wv.y * ev.y + wv.z * ev.z + wv.w * ev.w;
    }
#pragma unroll
    for (int o = 16; o; o >>= 1) s += __shfl_xor_sync(0xffffffffu, s, o);
    if (lane == 0) g_gi_enc[j] = s + b_ih[j];
}

__device__ __forceinline__ float sigm(float x) { return 1.f / (1.f + __expf(-x)); }
__device__ __forceinline__ float gru1(float ir, float iz, float in_,
                                      float hr, float hz, float hn, float h) {
    float r = sigm(ir + hr);
    float z = sigm(iz + hz);
    float n = tanhf(in_ + r * hn);
    return (1.f - z) * n + z * h;
}

// r0 = GRU(enc broadcast, h=sub) -> fp16 split (consumed only by gi0 GEMM)
__global__ void k_gru_r0(int S)
{
    int i = blockIdx.x * blockDim.x + threadIdx.x;
    if (i >= S * 192) return;
    int s = i / 192, d = (i - s * 192) * 4;
    const float* gh = g_gh + (size_t)s * DIM3;
    float4 ir  = *(const float4*)(g_gi_enc + d);
    float4 iz  = *(const float4*)(g_gi_enc + DIM + d);
    float4 in_ = *(const float4*)(g_gi_enc + 2 * DIM + d);
    float4 hr  = *(const float4*)(gh + d);
    float4 hz  = *(const float4*)(gh + DIM + d);
    float4 hn  = *(const float4*)(gh + 2 * DIM + d);
    float4 hh  = *(const float4*)(g_sub + (size_t)s * DIM + d);
    float4 o;
    o.x = gru1(ir.x, iz.x, in_.x, hr.x, hz.x, hn.x, hh.x);
    o.y = gru1(ir.y, iz.y, in_.y, hr.y, hz.y, hn.y, hh.y);
    o.z = gru1(ir.z, iz.z, in_.z, hr.z, hz.z, hn.z, hh.z);
    o.w = gru1(ir.w, iz.w, in_.w, hr.w, hz.w, hn.w, hh.w);
    uint2 hi, lo; split4(o, hi, lo);
    __half* row = g_r0s + (size_t)s * DIM2;
    *(uint2*)(row + d)       = hi;
    *(uint2*)(row + DIM + d) = lo;
}

__global__ void k_init(int N)
{
    int i = blockIdx.x * blockDim.x + threadIdx.x;
    if (i < N) { g_best[i] = -1; g_seedpos[i] = -1; }
}
__global__ void k_seed(const int* __restrict__ seeds, int S, int stride)
{
    int s = blockIdx.x * blockDim.x + threadIdx.x;
    if (s >= S) return;
    int node = seeds[s];
    g_seedpos[node] = s;
    atomicMax(&g_best[node], s * stride);
}
__global__ void k_edge(const int* __restrict__ heads, const int* __restrict__ tails,
                       int E, int stride)
{
    int e = blockIdx.x * blockDim.x + threadIdx.x;
    if (e >= E) return;
    int pos = g_seedpos[heads[e]];
    int t = pos * stride + 1 + e;
    atomicMax(&g_best[tails[e]], t);
}

// rj[e] = GRU(gi0[head], ghR[type], h=rel[type]) -> fp16 split
__global__ void k_rj(const int* __restrict__ heads, const int* __restrict__ types,
                     const float* __restrict__ rel)
{
    int e = blockIdx.x;
    int h = heads[e];
    int t = types[e];
    const float* gi = g_gi0 + (size_t)h * DIM3;
    const float* gh = g_ghR + (size_t)t * DIM3;
    const float* rl = rel + (size_t)t * DIM;
    int d = threadIdx.x * 4;
    float4 ir  = *(const float4*)(gi + d);
    float4 iz  = *(const float4*)(gi + DIM + d);
    float4 in_ = *(const float4*)(gi + 2 * DIM + d);
    float4 hr  = *(const float4*)(gh + d);
    float4 hz  = *(const float4*)(gh + DIM + d);
    float4 hn  = *(const float4*)(gh + 2 * DIM + d);
    float4 hh  = *(const float4*)(rl + d);
    float4 o;
    o.x = gru1(ir.x, iz.x, in_.x, hr.x, hz.x, hn.x, hh.x);
    o.y = gru1(ir.y, iz.y, in_.y, hr.y, hz.y, hn.y, hh.y);
    o.z = gru1(ir.z, iz.z, in_.z, hr.z, hz.z, hn.z, hh.z);
    o.w = gru1(ir.w, iz.w, in_.w, hr.w, hz.w, hn.w, hh.w);
    uint2 hi, lo; split4(o, hi, lo);
    __half* row = g_rjs + (size_t)e * DIM2;
    *(uint2*)(row + d)       = hi;
    *(uint2*)(row + DIM + d) = lo;
}

__global__ void k_out(const int* __restrict__ node2node, const int* __restrict__ old_nd,
                      const float* __restrict__ defa, float* __restrict__ out, int stride)
{
    int nrow = blockIdx.x;
    int id = node2node[old_nd[nrow]];
    int b = g_best[id];
    const float* src;
    if (b < 0) {
        src = defa + (size_t)nrow * DIM;
    } else {
        int q = b / stride;
        int rem = b - q * stride;
        src = (rem == 0) ? (g_sub + (size_t)q * DIM)
                         : (g_obj + (size_t)(rem - 1) * DIM);
    }
    int d = threadIdx.x * 4;
    *(float4*)(out + (size_t)nrow * DIM + d) = *(const float4*)(src + d);
}

// ================= host =================
extern "C" void kernel_launch(void* const* d_in, const int* in_sizes, int n_in,
                              void* d_out, int out_size)
{
    const float* enc   = (const float*)d_in[0];
    const float* smask = (const float*)d_in[1];
    const int*   seeds = (const int*)  d_in[2];
    const int*   ehead = (const int*)  d_in[3];
    const int*   etail = (const int*)  d_in[4];
    const int*   etype = (const int*)  d_in[5];
    const int*   n2n   = (const int*)  d_in[6];
    const int*   oldnd = (const int*)  d_in[7];
    const float* relE  = (const float*)d_in[8];
    const float* W_sub = (const float*)d_in[9];
    const float* b_sub = (const float*)d_in[10];
    const float* W_obj = (const float*)d_in[11];
    const float* b_obj = (const float*)d_in[12];
    const float* W_ih  = (const float*)d_in[13];
    const float* W_hh  = (const float*)d_in[14];
    const float* b_ih  = (const float*)d_in[15];
    const float* b_hh  = (const float*)d_in[16];
    const float* defa  = (const float*)d_in[17];
    float* out = (float*)d_out;

    const int S = in_sizes[2];
    const int E = in_sizes[3];
    const int N = in_sizes[6];
    const int R = in_sizes[8] / DIM;
    const int stride = E + 1;

    float *p_sub, *p_gh, *p_gi0, *p_ghR, *p_obj;
    __half *p_smasks, *p_subs, *p_r0s, *p_rjs, *p_rels,
           *p_Wsubs, *p_Wobjs, *p_Wihs, *p_Whhs;
    cudaGetSymbolAddress((void**)&p_sub,    g_sub);
    cudaGetSymbolAddress((void**)&p_gh,     g_gh);
    cudaGetSymbolAddress((void**)&p_gi0,    g_gi0);
    cudaGetSymbolAddress((void**)&p_ghR,    g_ghR);
    cudaGetSymbolAddress((void**)&p_obj,    g_obj);
    cudaGetSymbolAddress((void**)&p_smasks, g_smasks);
    cudaGetSymbolAddress((void**)&p_subs,   g_subs);
    cudaGetSymbolAddress((void**)&p_r0s,    g_r0s);
    cudaGetSymbolAddress((void**)&p_rjs,    g_rjs);
    cudaGetSymbolAddress((void**)&p_rels,   g_rels);
    cudaGetSymbolAddress((void**)&p_Wsubs,  g_Wsubs);
    cudaGetSymbolAddress((void**)&p_Wobjs,  g_Wobjs);
    cudaGetSymbolAddress((void**)&p_Wihs,   g_Wihs);
    cudaGetSymbolAddress((void**)&p_Whhs,   g_Whhs);

    cudaFuncSetAttribute(gemm_tc<1,1>, cudaFuncAttributeMaxDynamicSharedMemorySize, GEMM_SMEM);
    cudaFuncSetAttribute(gemm_tc<0,0>, cudaFuncAttributeMaxDynamicSharedMemorySize, GEMM_SMEM);
    cudaFuncSetAttribute(gemm_tc<1,0>, cudaFuncAttributeMaxDynamicSharedMemorySize, GEMM_SMEM);

    k_init<<<(N + 255) / 256, 256>>>(N);

    // A-operand splits (hi|lo) and W-operand halves (hi only)
    k_split<<<(S * 192 + 255) / 256, 256>>>(smask, p_smasks, S * 192);
    k_split<<<(R * 192 + 255) / 256, 256>>>(relE, p_rels, R * 192);
    k_half<<<(DIM * 192 + 255) / 256, 256>>>(W_sub, p_Wsubs, DIM * 192);
    k_half<<<(DIM * 192 + 255) / 256, 256>>>(W_obj, p_Wobjs, DIM * 192);
    k_half<<<(DIM3 * 192 + 255) / 256, 256>>>(W_ih, p_Wihs, DIM3 * 192);
    k_half<<<(DIM3 * 192 + 255) / 256, 256>>>(W_hh, p_Whhs, DIM3 * 192);

    k_gi_enc<<<(DIM3 + 7) / 8, 256>>>(enc, W_ih, b_ih);

    // sub = tanh(mask @ W_sub^T + b_sub)      [S,768], + split copy
    gemm_tc<1,1><<<dim3(DIM / 128, S / 128), 256, GEMM_SMEM>>>(
        p_smasks, p_Wsubs, b_sub, p_sub, p_subs, S, DIM);
    // gh = sub @ W_hh^T + b_hh                [S,2304]
    gemm_tc<0,0><<<dim3(DIM3 / 128, S / 128), 256, GEMM_SMEM>>>(
        p_subs, p_Whhs, b_hh, p_gh, (__half*)0, S, DIM3);
    // r0 = GRU(enc, sub) -> fp16 split
    k_gru_r0<<<(S * 192 + 255) / 256, 256>>>(S);
    // gi0 = r0 @ W_ih^T + b_ih                [S,2304]
    gemm_tc<0,0><<<dim3(DIM3 / 128, S / 128), 256, GEMM_SMEM>>>(
        p_r0s, p_Wihs, b_ih, p_gi0, (__half*)0, S, DIM3);
    // ghR = rel_emb @ W_hh^T + b_hh           [R,2304]
    gemm_tc<0,0><<<dim3(DIM3 / 128, (R + 127) / 128), 256, GEMM_SMEM>>>(
        p_rels, p_Whhs, b_hh, p_ghR, (__half*)0, R, DIM3);

    k_seed<<<(S + 255) / 256, 256>>>(seeds, S, stride);
    k_edge<<<(E + 255) / 256, 256>>>(ehead, etail, E, stride);

    // rj[e] = GRU(gi0[head], rel[type]) -> fp16 split
    k_rj<<<E, 192>>>(ehead, etype, relE);
    // obj = tanh(rj @ W_obj^T + b_obj)        [E,768]  (dominant GEMM)
    gemm_tc<1,0><<<dim3(DIM / 128, E / 128), 256, GEMM_SMEM>>>(
        p_rjs, p_Wobjs, b_obj, p_obj, (__half*)0, E, DIM);

    k_out<<<N, 192>>>(n2n, oldnd, defa, out, stride);
}